// round 5
// baseline (speedup 1.0000x reference)
#include <cuda_runtime.h>

// R4 resubmission (R2 tie-break-exact kernel; prior rounds failed on broker /
// device-busy infra errors before producing signal). Comment-only delta.

#define NT     131072
#define KC     1024
#define DIM    64
#define CHUNK  128            // codebook rows staged per iteration
#define KPC    (CHUNK/2)      // 64 k-pairs per chunk
#define NCHUNK (KC/CHUNK)     // 8
#define BLK    256
#define GRID_VQ (NT / BLK)    // 512 blocks, 1 token per thread

// deterministic loss partials (no atomics)
__device__ float g_partials[GRID_VQ];

static __device__ __forceinline__ unsigned long long pack2(float lo, float hi) {
    unsigned long long r;
    asm("mov.b64 %0, {%1, %2};" : "=l"(r) : "f"(lo), "f"(hi));
    return r;
}
static __device__ __forceinline__ void unpack2(unsigned long long v, float& lo, float& hi) {
    asm("mov.b64 {%0, %1}, %2;" : "=f"(lo), "=f"(hi) : "l"(v));
}
static __device__ __forceinline__ unsigned long long ffma2(unsigned long long a,
                                                           unsigned long long b,
                                                           unsigned long long c) {
    unsigned long long d;
    asm("fma.rn.f32x2 %0, %1, %2, %3;" : "=l"(d) : "l"(a), "l"(b), "l"(c));
    return d;
}
static __device__ __forceinline__ unsigned long long fadd2(unsigned long long a,
                                                           unsigned long long b) {
    unsigned long long d;
    asm("add.rn.f32x2 %0, %1, %2;" : "=l"(d) : "l"(a), "l"(b));
    return d;
}

__global__ __launch_bounds__(BLK, 1) void vq_kernel(
    const float* __restrict__ x, const float* __restrict__ w, float* __restrict__ out)
{
    // weight chunk, paired along k: sw[kp][d] = {w[2kp][d], w[2kp+1][d]}
    __shared__ __align__(16) float2 sw[KPC][DIM];   // 32 KB
    __shared__ float2 se[KC / 2];                   // e_norm pairs, 4 KB
    __shared__ float swarp[BLK / 32];

    const int tid = threadIdx.x;
    const int n = blockIdx.x * BLK + tid;

    // ---- e_norm for all 1024 codewords (pairs), once ----
    for (int p = tid; p < KC / 2; p += BLK) {
        const float4* r0 = (const float4*)(w + (size_t)(2 * p + 0) * DIM);
        const float4* r1 = (const float4*)(w + (size_t)(2 * p + 1) * DIM);
        float s0 = 0.f, s1 = 0.f;
        #pragma unroll
        for (int i = 0; i < DIM / 4; i++) {
            float4 a = r0[i]; float4 b = r1[i];
            s0 += a.x * a.x + a.y * a.y + a.z * a.z + a.w * a.w;
            s1 += b.x * b.x + b.y * b.y + b.z * b.z + b.w * b.w;
        }
        se[p] = make_float2(s0, s1);
    }

    // ---- own token: duplicated 64-bit lanes for f32x2, plus x_norm ----
    unsigned long long xd[DIM];   // 128 regs
    float xn = 0.f;
    {
        const float4* xr = (const float4*)(x + (size_t)n * DIM);
        #pragma unroll
        for (int i = 0; i < DIM / 4; i++) {
            float4 v = xr[i];
            xd[4 * i + 0] = pack2(v.x, v.x);
            xd[4 * i + 1] = pack2(v.y, v.y);
            xd[4 * i + 2] = pack2(v.z, v.z);
            xd[4 * i + 3] = pack2(v.w, v.w);
            xn += v.x * v.x + v.y * v.y + v.z * v.z + v.w * v.w;
        }
    }

    float best = 3.4e38f;
    int bi = 0;

    for (int c = 0; c < NCHUNK; c++) {
        __syncthreads();   // protect sw from previous iteration's readers (also covers se on c==0)
        // ---- stage chunk rows [c*128, c*128+128) in paired layout ----
        const float4* gw = (const float4*)(w + (size_t)c * CHUNK * DIM);
        for (int i = tid; i < CHUNK * DIM / 4; i += BLK) {
            float4 v = gw[i];
            int row = i >> 4;             // i*4 / 64
            int d0  = (i & 15) << 2;      // (i*4) % 64
            int kp  = row >> 1;
            if (row & 1) {
                sw[kp][d0 + 0].y = v.x; sw[kp][d0 + 1].y = v.y;
                sw[kp][d0 + 2].y = v.z; sw[kp][d0 + 3].y = v.w;
            } else {
                sw[kp][d0 + 0].x = v.x; sw[kp][d0 + 1].x = v.y;
                sw[kp][d0 + 2].x = v.z; sw[kp][d0 + 3].x = v.w;
            }
        }
        __syncthreads();

        const int kbase = c * CHUNK;
        for (int kp = 0; kp < KPC; kp++) {
            const ulonglong2* row = (const ulonglong2*)(&sw[kp][0]);
            unsigned long long a0 = 0ull, a1 = 0ull, a2 = 0ull, a3 = 0ull;
            #pragma unroll
            for (int j = 0; j < 32; j += 4) {
                ulonglong2 wa = row[j + 0];   // d = 2j, 2j+1   (broadcast LDS.128)
                ulonglong2 wb = row[j + 1];
                ulonglong2 wc = row[j + 2];
                ulonglong2 wdq = row[j + 3];
                a0 = ffma2(xd[2 * j + 0], wa.x, a0);
                a1 = ffma2(xd[2 * j + 1], wa.y, a1);
                a2 = ffma2(xd[2 * j + 2], wb.x, a2);
                a3 = ffma2(xd[2 * j + 3], wb.y, a3);
                a0 = ffma2(xd[2 * j + 4], wc.x, a0);
                a1 = ffma2(xd[2 * j + 5], wc.y, a1);
                a2 = ffma2(xd[2 * j + 6], wdq.x, a2);
                a3 = ffma2(xd[2 * j + 7], wdq.y, a3);
            }
            unsigned long long s = fadd2(fadd2(a0, a1), fadd2(a2, a3));
            float d0, d1;
            unpack2(s, d0, d1);
            float2 en = se[(kbase >> 1) + kp];
            // Reproduce the reference's fp32 rounding of the score:
            //   dist = fadd(fadd(x_norm, e_norm), -2*dot)   [*2 exact]
            // so exact grid-ties are broken by first index, matching
            // jnp.argmin over the reference's distance matrix.
            float sc0 = __fadd_rn(__fadd_rn(xn, en.x), -2.f * d0);
            float sc1 = __fadd_rn(__fadd_rn(xn, en.y), -2.f * d1);
            int k0 = kbase + 2 * kp;
            if (sc0 < best) { best = sc0; bi = k0; }       // strict <: first-min
            if (sc1 < best) { best = sc1; bi = k0 + 1; }   // tie-break, as argmin
        }
    }

    // ---- epilogue: gather codeword, write xq + index, per-token sq error ----
    const float4* wrow = (const float4*)(w + (size_t)bi * DIM);   // L2-resident
    float4* xqo = (float4*)(out + (size_t)n * DIM);
    float err = 0.f;
    #pragma unroll
    for (int i = 0; i < DIM / 4; i++) {
        float4 wv = wrow[i];
        float x0, x1, x2, x3, hx;
        unpack2(xd[4 * i + 0], x0, hx);
        unpack2(xd[4 * i + 1], x1, hx);
        unpack2(xd[4 * i + 2], x2, hx);
        unpack2(xd[4 * i + 3], x3, hx);
        float e0 = wv.x - x0, e1 = wv.y - x1, e2 = wv.z - x2, e3 = wv.w - x3;
        err += e0 * e0 + e1 * e1 + e2 * e2 + e3 * e3;
        xqo[i] = wv;
    }
    out[(size_t)NT * DIM + 1 + n] = (float)bi;   // embed_inds as f32

    // deterministic block reduction of err
    #pragma unroll
    for (int o = 16; o > 0; o >>= 1) err += __shfl_xor_sync(0xffffffffu, err, o);
    if ((tid & 31) == 0) swarp[tid >> 5] = err;
    __syncthreads();
    if (tid == 0) {
        float s = 0.f;
        #pragma unroll
        for (int i = 0; i < BLK / 32; i++) s += swarp[i];
        g_partials[blockIdx.x] = s;
    }
}

__global__ void finalize_kernel(float* __restrict__ out) {
    __shared__ double sd[256];
    int tid = threadIdx.x;
    double v = 0.0;
    for (int i = tid; i < GRID_VQ; i += 256) v += (double)g_partials[i];
    sd[tid] = v;
    __syncthreads();
    for (int o = 128; o > 0; o >>= 1) {
        if (tid < o) sd[tid] += sd[tid + o];
        __syncthreads();
    }
    if (tid == 0) {
        double mse = sd[0] / ((double)NT * (double)DIM);
        out[(size_t)NT * DIM] = (float)(1.25 * mse);   // codebook + 0.25*commitment
    }
}

extern "C" void kernel_launch(void* const* d_in, const int* in_sizes, int n_in,
                              void* d_out, int out_size) {
    const float* x = (const float*)d_in[0];
    const float* w = (const float*)d_in[1];
    float* out = (float*)d_out;
    vq_kernel<<<GRID_VQ, BLK>>>(x, w, out);
    finalize_kernel<<<1, 256>>>(out);
}